// round 10
// baseline (speedup 1.0000x reference)
#include <cuda_runtime.h>
#include <cuda_bf16.h>
#include <cstdint>

// Problem constants
#define B_ 16
#define T_ 16384
#define D_ 256
#define S_ 4
#define TILE 128
#define KT 128                 // t per gram iteration (128 int8 = 128B rows)
#define KSPLIT 6               // 48*6 = 288 CTAs = 2 per SM
#define SPITCH 144             // 128B data + 16B pad: conflict-free ldmatrix
#define STAGE (TILE * SPITCH)  // 18432 B per matrix stage
#define NRED 400               // 384 Gvv blocks + 16 Gvy/count blocks

// Scratch (device globals; zero-initialized at load)
__device__ signed char g_Vq[(size_t)B_ * D_ * T_];          // int8 V^T [b][d][t] (64MB)
__device__ unsigned char g_cls[B_ * T_];                     // speaker class per row
__device__ int   g_GvvP[(size_t)48 * KSPLIT * TILE * TILE];  // s32 K-split partials (18.9MB)
__device__ float g_GvyP[512 * 1024];                         // per-block Gvy partials (2MB)
__device__ float g_acc[1];
__device__ unsigned int g_done;

// ---------------------------------------------------------------------------
// PTX helpers
// ---------------------------------------------------------------------------
__device__ __forceinline__ uint32_t prmt(uint32_t a, uint32_t b, uint32_t c) {
    uint32_t d;
    asm("prmt.b32 %0, %1, %2, %3;" : "=r"(d) : "r"(a), "r"(b), "r"(c));
    return d;
}
__device__ __forceinline__ void cp16(void* dst, const void* src) {
    unsigned d = (unsigned)__cvta_generic_to_shared(dst);
    asm volatile("cp.async.cg.shared.global [%0], [%1], 16;\n" :: "r"(d), "l"(src));
}
__device__ __forceinline__ void cp_commit() { asm volatile("cp.async.commit_group;\n"); }
template <int N> __device__ __forceinline__ void cp_wait() {
    asm volatile("cp.async.wait_group %0;\n" :: "n"(N));
}
// non-transposed ldmatrix x4 (b16): m0=rows0-7/B0-15, m1=rows8-15/B0-15,
// m2=rows0-7/B16-31, m3=rows8-15/B16-31; per-thread bytes match s8 frags.
__device__ __forceinline__ void ldsm4(uint32_t* r, const void* p) {
    unsigned a = (unsigned)__cvta_generic_to_shared(p);
    asm volatile("ldmatrix.sync.aligned.m8n8.x4.shared.b16 {%0,%1,%2,%3}, [%4];\n"
                 : "=r"(r[0]), "=r"(r[1]), "=r"(r[2]), "=r"(r[3]) : "r"(a));
}
__device__ __forceinline__ void mma_s8(int* c, const uint32_t* a, const uint32_t* b) {
    asm volatile("mma.sync.aligned.m16n8k32.row.col.s32.s8.s8.s32 "
                 "{%0,%1,%2,%3},{%4,%5,%6,%7},{%8,%9},{%0,%1,%2,%3};\n"
                 : "+r"(c[0]), "+r"(c[1]), "+r"(c[2]), "+r"(c[3])
                 : "r"(a[0]), "r"(a[1]), "r"(a[2]), "r"(a[3]), "r"(b[0]), "r"(b[1]));
}

// ---------------------------------------------------------------------------
// K1: fused L2 normalize + class + Gvy partials + INT8 TRANSPOSED output.
// 512 blocks, 8 warps; warp = 64 rows in 8-row batches (two 4-row interleaved
// butterfly groups). Per batch: quantize to s8, PRMT-pack, PRMT-transpose,
// store uint2 (8 t) per d.
// ---------------------------------------------------------------------------
__global__ __launch_bounds__(256) void k_norm(const float* __restrict__ emb,
                                              const float* __restrict__ lab) {
    __shared__ float sred[8 * 1024];
    int b    = blockIdx.x >> 5;
    int ch   = blockIdx.x & 31;
    int wid  = threadIdx.x >> 5, lane = threadIdx.x & 31;
    int tloc = ch * 512 + wid * 64;       // within-batch t base for this warp
    int row0 = b * T_ + tloc;

    // coalesced class pre-load
    int s_lo, s_hi;
    {
        float4 lb = reinterpret_cast<const float4*>(lab)[row0 + lane];
        s_lo = lb.y > 0.5f ? 1 : (lb.z > 0.5f ? 2 : (lb.w > 0.5f ? 3 : 0));
        g_cls[row0 + lane] = (unsigned char)s_lo;
        float4 lb2 = reinterpret_cast<const float4*>(lab)[row0 + 32 + lane];
        s_hi = lb2.y > 0.5f ? 1 : (lb2.z > 0.5f ? 2 : (lb2.w > 0.5f ? 3 : 0));
        g_cls[row0 + 32 + lane] = (unsigned char)s_hi;
    }

    float acc[4][8];
    #pragma unroll
    for (int c = 0; c < 4; c++)
        #pragma unroll
        for (int i = 0; i < 8; i++) acc[c][i] = 0.0f;

    #pragma unroll 1
    for (int batch = 0; batch < 8; ++batch) {
        uint32_t P[8][2];   // packed s8 per row: [rb][j], j=0 -> d 8l..+3, j=1 -> 8l+4..+7
        #pragma unroll
        for (int g = 0; g < 2; ++g) {
            // batch 8 independent LDG.128
            float4 va[4][2];
            #pragma unroll
            for (int u = 0; u < 4; u++) {
                const float4* src = reinterpret_cast<const float4*>(emb)
                                  + (size_t)(row0 + batch * 8 + g * 4 + u) * (D_ / 4) + lane * 2;
                va[u][0] = src[0];
                va[u][1] = src[1];
            }
            // 4 interleaved butterflies
            float ss[4];
            #pragma unroll
            for (int u = 0; u < 4; u++) {
                float4 v0 = va[u][0], v1 = va[u][1];
                ss[u] = v0.x*v0.x + v0.y*v0.y + v0.z*v0.z + v0.w*v0.w
                      + v1.x*v1.x + v1.y*v1.y + v1.z*v1.z + v1.w*v1.w;
            }
            #pragma unroll
            for (int o = 16; o; o >>= 1) {
                #pragma unroll
                for (int u = 0; u < 4; u++)
                    ss[u] += __shfl_xor_sync(0xffffffffu, ss[u], o);
            }
            #pragma unroll
            for (int u = 0; u < 4; u++) {
                int r = batch * 8 + g * 4 + u;
                float sc = 1.0f / fmaxf(sqrtf(ss[u]), 1e-12f);
                float4 v0 = va[u][0], v1 = va[u][1];
                float n0 = v0.x * sc, n1 = v0.y * sc, n2 = v0.z * sc, n3 = v0.w * sc;
                float n4 = v1.x * sc, n5 = v1.y * sc, n6 = v1.z * sc, n7 = v1.w * sc;

                // quantize to s8 (|n|<=1 -> |q|<=127, no clamp needed)
                uint32_t q0 = (uint32_t)__float2int_rn(n0 * 127.0f);
                uint32_t q1 = (uint32_t)__float2int_rn(n1 * 127.0f);
                uint32_t q2 = (uint32_t)__float2int_rn(n2 * 127.0f);
                uint32_t q3 = (uint32_t)__float2int_rn(n3 * 127.0f);
                uint32_t q4 = (uint32_t)__float2int_rn(n4 * 127.0f);
                uint32_t q5 = (uint32_t)__float2int_rn(n5 * 127.0f);
                uint32_t q6 = (uint32_t)__float2int_rn(n6 * 127.0f);
                uint32_t q7 = (uint32_t)__float2int_rn(n7 * 127.0f);
                P[g * 4 + u][0] = prmt(prmt(q0, q1, 0x0040), prmt(q2, q3, 0x0040), 0x5410);
                P[g * 4 + u][1] = prmt(prmt(q4, q5, 0x0040), prmt(q6, q7, 0x0040), 0x5410);

                int s = __shfl_sync(0xffffffffu, r < 32 ? s_lo : s_hi, r & 31);
                #define ACCUM(C) { acc[C][0]+=n0; acc[C][1]+=n1; acc[C][2]+=n2; acc[C][3]+=n3; \
                                   acc[C][4]+=n4; acc[C][5]+=n5; acc[C][6]+=n6; acc[C][7]+=n7; }
                if      (s == 0) ACCUM(0)
                else if (s == 1) ACCUM(1)
                else if (s == 2) ACCUM(2)
                else             ACCUM(3)
                #undef ACCUM
            }
        }
        // in-lane byte transpose: per d (= 8*lane + 4j + c), 8 t-bytes -> uint2
        #pragma unroll
        for (int j = 0; j < 2; ++j) {
            #pragma unroll
            for (int c = 0; c < 4; ++c) {
                uint32_t sel = 0x0040u + (uint32_t)c * 0x0011u;
                uint32_t lo  = prmt(prmt(P[0][j], P[1][j], sel),
                                    prmt(P[2][j], P[3][j], sel), 0x5410);
                uint32_t hi  = prmt(prmt(P[4][j], P[5][j], sel),
                                    prmt(P[6][j], P[7][j], sel), 0x5410);
                int d = lane * 8 + j * 4 + c;
                *reinterpret_cast<uint2*>(g_Vq + (((size_t)(b * D_ + d)) << 14)
                                          + tloc + batch * 8) = make_uint2(lo, hi);
            }
        }
    }

    // cross-warp Gvy reduce: sred[wid][(c*8+i)*32 + lane]  (conflict-free)
    #pragma unroll
    for (int c = 0; c < 4; c++)
        #pragma unroll
        for (int i = 0; i < 8; i++)
            sred[wid * 1024 + (c * 8 + i) * 32 + lane] = acc[c][i];
    __syncthreads();

    float* gp = g_GvyP + (size_t)blockIdx.x * 1024;
    #pragma unroll
    for (int j = 0; j < 4; j++) {
        int o = threadIdx.x + 256 * j;
        float sum = 0.0f;
        #pragma unroll
        for (int w = 0; w < 8; w++) sum += sred[w * 1024 + o];
        gp[o] = sum;
    }
}

// ---------------------------------------------------------------------------
// K2: int8 Gram tiles Gvv = Vq Vq^T (over t). grid (48, 6) = 288 CTAs = 2/SM.
// Per iter: 128 d-rows x 128 t int8 per matrix (pitch 144), 4 k-steps of 32,
// m16n8k32 s8 mma with s32 accum. 2-stage ring, one __syncthreads per iter.
// K-iterations: 22,22,21,21,21,21 (sum 128).
// ---------------------------------------------------------------------------
__global__ __launch_bounds__(256, 2) void k_gram() {
    extern __shared__ char sm[];
    int bt   = blockIdx.x;
    int b    = bt / 3, tile = bt % 3;
    int ti   = (tile == 0) ? 0 : 1;
    int tj   = (tile == 2) ? 1 : 0;
    bool diag = (ti == tj);
    int kc   = blockIdx.y;
    int it0  = (kc < 2) ? 22 * kc : 44 + 21 * (kc - 2);
    int NIT  = (kc < 2) ? 22 : 21;
    int tid  = threadIdx.x;

    const signed char* base_i = g_Vq + (((size_t)(b * D_ + ti * TILE)) << 14);
    const signed char* base_j = g_Vq + (((size_t)(b * D_ + tj * TILE)) << 14);

    int wid = tid >> 5, lane = tid & 31;
    int wm = (wid & 3) * 32;
    int wn = (wid >> 2) * 64;

    int acc[2][8][4];
    #pragma unroll
    for (int mi = 0; mi < 2; mi++)
        #pragma unroll
        for (int ni = 0; ni < 8; ni++)
            #pragma unroll
            for (int x = 0; x < 4; x++) acc[mi][ni][x] = 0;

    auto load_stage = [&](int st, int iter) {
        int kt0 = (it0 + iter) * KT;
        char* sa = sm + st * STAGE;
        #pragma unroll
        for (int i = 0; i < 4; i++) {
            int c = tid + i * 256;      // 1024 chunks: 128 rows x 8 x 16B
            int r = c >> 3, col = c & 7;
            cp16(sa + r * SPITCH + col * 16, base_i + ((size_t)r << 14) + kt0 + col * 16);
        }
        if (!diag) {
            char* sb = sm + 2 * STAGE + st * STAGE;
            #pragma unroll
            for (int i = 0; i < 4; i++) {
                int c = tid + i * 256;
                int r = c >> 3, col = c & 7;
                cp16(sb + r * SPITCH + col * 16, base_j + ((size_t)r << 14) + kt0 + col * 16);
            }
        }
        cp_commit();
    };

    load_stage(0, 0);

    int lrow = lane & 15;               // ldmatrix row within 16-row fragment
    int lcol = (lane >> 4) * 16;        // byte column 0 / 16

    for (int it = 0; it < NIT; ++it) {
        cp_wait<0>();
        __syncthreads();
        if (it + 1 < NIT) load_stage((it + 1) & 1, it + 1);

        int st = it & 1;
        const char* As = sm + st * STAGE;
        const char* Bs = diag ? As : sm + 2 * STAGE + st * STAGE;
        #pragma unroll
        for (int ks = 0; ks < 4; ++ks) {
            int kb = ks * 32 + lcol;
            uint32_t af[2][4];
            #pragma unroll
            for (int mi = 0; mi < 2; mi++)
                ldsm4(af[mi], As + (wm + mi * 16 + lrow) * SPITCH + kb);
            uint32_t bfr[8][2];
            #pragma unroll
            for (int nj = 0; nj < 4; nj++) {
                uint32_t t4[4];
                ldsm4(t4, Bs + (wn + nj * 16 + lrow) * SPITCH + kb);
                bfr[2 * nj][0]     = t4[0]; bfr[2 * nj][1]     = t4[2];
                bfr[2 * nj + 1][0] = t4[1]; bfr[2 * nj + 1][1] = t4[3];
            }
            #pragma unroll
            for (int mi = 0; mi < 2; mi++)
                #pragma unroll
                for (int ni = 0; ni < 8; ni++)
                    mma_s8(acc[mi][ni], af[mi], bfr[ni]);
        }
    }

    // Epilogue: plain stores of this K-split's s32 partial tile
    int gid = lane >> 2, tig = lane & 3;
    int* gdst = g_GvvP + ((size_t)bt * KSPLIT + kc) * TILE * TILE;
    #pragma unroll
    for (int mi = 0; mi < 2; mi++) {
        #pragma unroll
        for (int ni = 0; ni < 8; ni++) {
            int m = wm + mi * 16 + gid;
            int n = wn + ni * 8 + tig * 2;
            int* p = gdst + m * TILE + n;
            p[0] = acc[mi][ni][0];
            p[1] = acc[mi][ni][1];
            p[8 * TILE + 0] = acc[mi][ni][2];
            p[8 * TILE + 1] = acc[mi][ni][3];
        }
    }
}

// ---------------------------------------------------------------------------
// K3: parallel reduction + final output. 400 blocks.
// ---------------------------------------------------------------------------
__device__ float blockSum(float v) {
    __shared__ float sw[8];
    int lane = threadIdx.x & 31, w = threadIdx.x >> 5;
    __syncthreads();
    #pragma unroll
    for (int o = 16; o; o >>= 1) v += __shfl_xor_sync(0xffffffffu, v, o);
    if (lane == 0) sw[w] = v;
    __syncthreads();
    v = (threadIdx.x < 8) ? sw[threadIdx.x] : 0.0f;
    if (w == 0)
        #pragma unroll
        for (int o = 4; o; o >>= 1) v += __shfl_xor_sync(0xffu, v, o);
    return v;
}

__global__ __launch_bounds__(256) void k_red(float* __restrict__ out) {
    int bid = blockIdx.x, tid = threadIdx.x;
    const float invq2 = 1.0f / 16129.0f;   // 1/127^2
    if (bid < 384) {
        int bt = bid >> 3, seg = bid & 7;
        const int* g = g_GvvP + (size_t)bt * KSPLIT * TILE * TILE + seg * 2048;
        float total = 0.0f;
        #pragma unroll 2
        for (int i = tid; i < 2048; i += 256) {
            int xs = 0;
            #pragma unroll
            for (int kc = 0; kc < KSPLIT; kc++) xs += g[kc * TILE * TILE + i];
            float x = (float)xs * invq2;
            total += x * x;
        }
        total = blockSum(total);
        if (tid == 0) {
            float w = (bt % 3 == 1) ? 2.0f : 1.0f;  // off-diagonal tile counts twice
            atomicAdd(g_acc, w * total);
        }
    } else {
        int b = bid - 384;
        const float* gp = g_GvyP + (size_t)b * 32 * 1024;
        float gy = 0.0f;
        #pragma unroll
        for (int j = 0; j < 4; j++) {
            int o = tid + 256 * j;
            float x = 0.0f;
            #pragma unroll
            for (int ch = 0; ch < 32; ch++) x += gp[ch * 1024 + o];
            gy += x * x;
        }
        float c0 = 0, c1 = 0, c2 = 0, c3 = 0;
        for (int t = tid; t < T_; t += 256) {
            int s = g_cls[b * T_ + t];
            c0 += (s == 0); c1 += (s == 1); c2 += (s == 2); c3 += (s == 3);
        }
        gy = blockSum(gy);
        c0 = blockSum(c0); c1 = blockSum(c1); c2 = blockSum(c2); c3 = blockSum(c3);
        if (tid == 0)
            atomicAdd(g_acc, -2.0f * gy + c0 * c0 + c1 * c1 + c2 * c2 + c3 * c3);
    }
    if (tid == 0) {
        __threadfence();
        unsigned old = atomicAdd(&g_done, 1u);
        if (old == NRED - 1) {
            // divide by T*T*B = 2^32 (exact power of two)
            out[0] = g_acc[0] * 2.3283064365386963e-10f;
            g_acc[0] = 0.0f;
            g_done = 0u;
        }
    }
}

// ---------------------------------------------------------------------------
extern "C" void kernel_launch(void* const* d_in, const int* in_sizes, int n_in,
                              void* d_out, int out_size) {
    const float* emb = (const float*)d_in[0];
    const float* lab = (const float*)d_in[1];
    float* out = (float*)d_out;
    (void)in_sizes; (void)n_in; (void)out_size;

    const int smem_bytes = 4 * STAGE;   // 73728
    cudaFuncSetAttribute(k_gram, cudaFuncAttributeMaxDynamicSharedMemorySize, smem_bytes);

    k_norm<<<512, 256>>>(emb, lab);     // fused normalize + quantize + transpose + Gvy
    dim3 g2(48, KSPLIT);
    k_gram<<<g2, 256, smem_bytes>>>();
    k_red<<<NRED, 256>>>(out);
}

// round 11
// speedup vs baseline: 1.0738x; 1.0738x over previous
#include <cuda_runtime.h>
#include <cuda_bf16.h>
#include <cstdint>

// Problem constants
#define B_ 16
#define T_ 16384
#define D_ 256
#define S_ 4
#define TILE 128
#define KT 128                 // t per gram iteration = 8 tc chunks
#define KSPLIT 6               // 48*6 = 288 CTAs = 2 per SM
#define SPITCH 144             // 128B data + 16B pad: conflict-free ldmatrix
#define STAGE (TILE * SPITCH)  // 18432 B per matrix stage
#define NRED 400               // 384 Gvv blocks + 16 Gvy/count blocks

// int8 V^T in 16-t chunks: g_Vq[b][tc][d][16], tc = t/16 (64MB).
// (d, tc) slot = 16 contiguous bytes; consecutive d contiguous -> coalesced.
__device__ signed char g_Vq[(size_t)B_ * 1024 * D_ * 16];
__device__ unsigned char g_cls[B_ * T_];
__device__ int   g_GvvP[(size_t)48 * KSPLIT * TILE * TILE];  // s32 K-split partials
__device__ float g_GvyP[512 * 1024];                         // per-block Gvy partials
__device__ float g_acc[1];
__device__ unsigned int g_done;

// ---------------------------------------------------------------------------
// PTX helpers
// ---------------------------------------------------------------------------
__device__ __forceinline__ uint32_t prmt(uint32_t a, uint32_t b, uint32_t c) {
    uint32_t d;
    asm("prmt.b32 %0, %1, %2, %3;" : "=r"(d) : "r"(a), "r"(b), "r"(c));
    return d;
}
__device__ __forceinline__ void cp16(void* dst, const void* src) {
    unsigned d = (unsigned)__cvta_generic_to_shared(dst);
    asm volatile("cp.async.cg.shared.global [%0], [%1], 16;\n" :: "r"(d), "l"(src));
}
__device__ __forceinline__ void cp_commit() { asm volatile("cp.async.commit_group;\n"); }
template <int N> __device__ __forceinline__ void cp_wait() {
    asm volatile("cp.async.wait_group %0;\n" :: "n"(N));
}
__device__ __forceinline__ void ldsm4(uint32_t* r, const void* p) {
    unsigned a = (unsigned)__cvta_generic_to_shared(p);
    asm volatile("ldmatrix.sync.aligned.m8n8.x4.shared.b16 {%0,%1,%2,%3}, [%4];\n"
                 : "=r"(r[0]), "=r"(r[1]), "=r"(r[2]), "=r"(r[3]) : "r"(a));
}
__device__ __forceinline__ void mma_s8(int* c, const uint32_t* a, const uint32_t* b) {
    asm volatile("mma.sync.aligned.m16n8k32.row.col.s32.s8.s8.s32 "
                 "{%0,%1,%2,%3},{%4,%5,%6,%7},{%8,%9},{%0,%1,%2,%3};\n"
                 : "+r"(c[0]), "+r"(c[1]), "+r"(c[2]), "+r"(c[3])
                 : "r"(a[0]), "r"(a[1]), "r"(a[2]), "r"(a[3]), "r"(b[0]), "r"(b[1]));
}

// ---------------------------------------------------------------------------
// K1: fused L2 normalize + class + Gvy partials + int8 transposed output via
// smem-staged coalesced stores. 512 blocks, 8 warps, warp = 64 t (4 tc).
// Per tc (16 t = 2 row-batches): in-lane PRMT transpose -> per-warp 4KB
// swizzled staging -> 8 coalesced STG.128 (512B each).
// ---------------------------------------------------------------------------
__global__ __launch_bounds__(256) void k_norm(const float* __restrict__ emb,
                                              const float* __restrict__ lab) {
    __shared__ uint4 sstage[2048];               // 32KB: staging, reused as sred
    char*  sp   = reinterpret_cast<char*>(sstage);
    float* sred = reinterpret_cast<float*>(sstage);

    int b    = blockIdx.x >> 5;
    int ch   = blockIdx.x & 31;
    int wid  = threadIdx.x >> 5, lane = threadIdx.x & 31;
    int tloc = ch * 512 + wid * 64;
    int row0 = b * T_ + tloc;
    uint32_t sb = wid * 4096;                    // per-warp staging byte base

    // coalesced class pre-load
    int s_lo, s_hi;
    {
        float4 lb = reinterpret_cast<const float4*>(lab)[row0 + lane];
        s_lo = lb.y > 0.5f ? 1 : (lb.z > 0.5f ? 2 : (lb.w > 0.5f ? 3 : 0));
        g_cls[row0 + lane] = (unsigned char)s_lo;
        float4 lb2 = reinterpret_cast<const float4*>(lab)[row0 + 32 + lane];
        s_hi = lb2.y > 0.5f ? 1 : (lb2.z > 0.5f ? 2 : (lb2.w > 0.5f ? 3 : 0));
        g_cls[row0 + 32 + lane] = (unsigned char)s_hi;
    }

    float acc[4][8];
    #pragma unroll
    for (int c = 0; c < 4; c++)
        #pragma unroll
        for (int i = 0; i < 8; i++) acc[c][i] = 0.0f;

    uint4* gout = reinterpret_cast<uint4*>(g_Vq);

    #pragma unroll 1
    for (int half = 0; half < 4; ++half) {       // one tc (16 t) per half
        uint2 TT[2][8];                          // [batch parity][d-slot] = 8 t bytes
        #pragma unroll
        for (int pb = 0; pb < 2; ++pb) {
            int batch = half * 2 + pb;
            uint32_t P[8][2];
            #pragma unroll
            for (int g = 0; g < 2; ++g) {
                float4 va[4][2];
                #pragma unroll
                for (int u = 0; u < 4; u++) {
                    const float4* src = reinterpret_cast<const float4*>(emb)
                        + (size_t)(row0 + batch * 8 + g * 4 + u) * (D_ / 4) + lane * 2;
                    va[u][0] = src[0];
                    va[u][1] = src[1];
                }
                float ss[4];
                #pragma unroll
                for (int u = 0; u < 4; u++) {
                    float4 v0 = va[u][0], v1 = va[u][1];
                    ss[u] = v0.x*v0.x + v0.y*v0.y + v0.z*v0.z + v0.w*v0.w
                          + v1.x*v1.x + v1.y*v1.y + v1.z*v1.z + v1.w*v1.w;
                }
                #pragma unroll
                for (int o = 16; o; o >>= 1) {
                    #pragma unroll
                    for (int u = 0; u < 4; u++)
                        ss[u] += __shfl_xor_sync(0xffffffffu, ss[u], o);
                }
                #pragma unroll
                for (int u = 0; u < 4; u++) {
                    int r = batch * 8 + g * 4 + u;
                    float sc = 1.0f / fmaxf(sqrtf(ss[u]), 1e-12f);
                    float4 v0 = va[u][0], v1 = va[u][1];
                    float n0 = v0.x * sc, n1 = v0.y * sc, n2 = v0.z * sc, n3 = v0.w * sc;
                    float n4 = v1.x * sc, n5 = v1.y * sc, n6 = v1.z * sc, n7 = v1.w * sc;

                    uint32_t q0 = (uint32_t)__float2int_rn(n0 * 127.0f);
                    uint32_t q1 = (uint32_t)__float2int_rn(n1 * 127.0f);
                    uint32_t q2 = (uint32_t)__float2int_rn(n2 * 127.0f);
                    uint32_t q3 = (uint32_t)__float2int_rn(n3 * 127.0f);
                    uint32_t q4 = (uint32_t)__float2int_rn(n4 * 127.0f);
                    uint32_t q5 = (uint32_t)__float2int_rn(n5 * 127.0f);
                    uint32_t q6 = (uint32_t)__float2int_rn(n6 * 127.0f);
                    uint32_t q7 = (uint32_t)__float2int_rn(n7 * 127.0f);
                    P[g * 4 + u][0] = prmt(prmt(q0, q1, 0x0040), prmt(q2, q3, 0x0040), 0x5410);
                    P[g * 4 + u][1] = prmt(prmt(q4, q5, 0x0040), prmt(q6, q7, 0x0040), 0x5410);

                    int s = __shfl_sync(0xffffffffu, r < 32 ? s_lo : s_hi, r & 31);
                    #define ACCUM(C) { acc[C][0]+=n0; acc[C][1]+=n1; acc[C][2]+=n2; acc[C][3]+=n3; \
                                       acc[C][4]+=n4; acc[C][5]+=n5; acc[C][6]+=n6; acc[C][7]+=n7; }
                    if      (s == 0) ACCUM(0)
                    else if (s == 1) ACCUM(1)
                    else if (s == 2) ACCUM(2)
                    else             ACCUM(3)
                    #undef ACCUM
                }
            }
            // in-lane transpose: slot o = j*4+c -> d = 8*lane + o, 8 t bytes
            #pragma unroll
            for (int j = 0; j < 2; ++j) {
                #pragma unroll
                for (int c = 0; c < 4; ++c) {
                    uint32_t sel = 0x0040u + (uint32_t)c * 0x0011u;
                    uint32_t lo  = prmt(prmt(P[0][j], P[1][j], sel),
                                        prmt(P[2][j], P[3][j], sel), 0x5410);
                    uint32_t hi  = prmt(prmt(P[4][j], P[5][j], sel),
                                        prmt(P[6][j], P[7][j], sel), 0x5410);
                    TT[pb][j * 4 + c] = make_uint2(lo, hi);
                }
            }
        }
        // stage: phys(d) = 128*(d>>3) + 16*(((d&7)+(d>>3))&7); d = 8*lane + o
        #pragma unroll
        for (int o = 0; o < 8; ++o) {
            uint32_t addr = sb + 128u * lane + ((((unsigned)(o + lane)) & 7u) << 4);
            *reinterpret_cast<uint4*>(sp + addr) =
                make_uint4(TT[0][o].x, TT[0][o].y, TT[1][o].x, TT[1][o].y);
        }
        __syncwarp();
        // drain: round k covers d = 32k..32k+31 -> one 512B coalesced STG.128
        size_t gbase = ((size_t)(b * 1024 + (tloc >> 4) + half)) << 8;
        #pragma unroll
        for (int k = 0; k < 8; ++k) {
            int g = 4 * k + (lane >> 3);
            int o = lane & 7;
            uint4 v = *reinterpret_cast<uint4*>(
                sp + sb + 128u * g + ((((unsigned)(o + g)) & 7u) << 4));
            gout[gbase + 32 * k + lane] = v;
        }
        __syncwarp();
    }

    // cross-warp Gvy reduce (staging buffer reused; each warp owns its slice)
    #pragma unroll
    for (int c = 0; c < 4; c++)
        #pragma unroll
        for (int i = 0; i < 8; i++)
            sred[wid * 1024 + (c * 8 + i) * 32 + lane] = acc[c][i];
    __syncthreads();

    float* gp = g_GvyP + (size_t)blockIdx.x * 1024;
    #pragma unroll
    for (int j = 0; j < 4; j++) {
        int o = threadIdx.x + 256 * j;
        float sum = 0.0f;
        #pragma unroll
        for (int w = 0; w < 8; w++) sum += sred[w * 1024 + o];
        gp[o] = sum;
    }
}

// ---------------------------------------------------------------------------
// K2: int8 Gram tiles Gvv = Vq Vq^T (over t). grid (48, 6) = 288 CTAs = 2/SM.
// Per iter: 128 d-rows x 128 t (8 tc) per matrix, contiguous global reads,
// 4 k-steps of m16n8k32 s8 mma, s32 accum. 2-stage ring, one sync per iter.
// K-iterations: 22,22,21,21,21,21 (sum 128).
// ---------------------------------------------------------------------------
__global__ __launch_bounds__(256, 2) void k_gram() {
    extern __shared__ char sm[];
    int bt   = blockIdx.x;
    int b    = bt / 3, tile = bt % 3;
    int ti   = (tile == 0) ? 0 : 1;
    int tj   = (tile == 2) ? 1 : 0;
    bool diag = (ti == tj);
    int kc   = blockIdx.y;
    int it0  = (kc < 2) ? 22 * kc : 44 + 21 * (kc - 2);
    int NIT  = (kc < 2) ? 22 : 21;
    int tid  = threadIdx.x;

    // address of (b, tc, d) slot: ((b*1024 + tc)*256 + d) * 16
    const signed char* base_i = g_Vq + (((size_t)b * 1024 * 256 + ti * TILE) << 4);
    const signed char* base_j = g_Vq + (((size_t)b * 1024 * 256 + tj * TILE) << 4);

    int wid = tid >> 5, lane = tid & 31;
    int wm = (wid & 3) * 32;
    int wn = (wid >> 2) * 64;

    int acc[2][8][4];
    #pragma unroll
    for (int mi = 0; mi < 2; mi++)
        #pragma unroll
        for (int ni = 0; ni < 8; ni++)
            #pragma unroll
            for (int x = 0; x < 4; x++) acc[mi][ni][x] = 0;

    auto load_stage = [&](int st, int iter) {
        size_t tc0 = (size_t)(it0 + iter) * 8;   // 8 tc chunks per iteration
        char* sa = sm + st * STAGE;
        #pragma unroll
        for (int i = 0; i < 4; i++) {
            int c = tid + i * 256;               // 1024: q = tc sub (0..7), dd = d
            int q = c >> 7, dd = c & 127;
            cp16(sa + dd * SPITCH + q * 16,
                 base_i + (((tc0 + q) * 256 + dd) << 4));
        }
        if (!diag) {
            char* sb = sm + 2 * STAGE + st * STAGE;
            #pragma unroll
            for (int i = 0; i < 4; i++) {
                int c = tid + i * 256;
                int q = c >> 7, dd = c & 127;
                cp16(sb + dd * SPITCH + q * 16,
                     base_j + (((tc0 + q) * 256 + dd) << 4));
            }
        }
        cp_commit();
    };

    load_stage(0, 0);

    int lrow = lane & 15;
    int lcol = (lane >> 4) * 16;

    for (int it = 0; it < NIT; ++it) {
        cp_wait<0>();
        __syncthreads();
        if (it + 1 < NIT) load_stage((it + 1) & 1, it + 1);

        int st = it & 1;
        const char* As = sm + st * STAGE;
        const char* Bs = diag ? As : sm + 2 * STAGE + st * STAGE;
        #pragma unroll
        for (int ks = 0; ks < 4; ++ks) {
            int kb = ks * 32 + lcol;
            uint32_t af[2][4];
            #pragma unroll
            for (int mi = 0; mi < 2; mi++)
                ldsm4(af[mi], As + (wm + mi * 16 + lrow) * SPITCH + kb);
            uint32_t bfr[8][2];
            #pragma unroll
            for (int nj = 0; nj < 4; nj++) {
                uint32_t t4[4];
                ldsm4(t4, Bs + (wn + nj * 16 + lrow) * SPITCH + kb);
                bfr[2 * nj][0]     = t4[0]; bfr[2 * nj][1]     = t4[2];
                bfr[2 * nj + 1][0] = t4[1]; bfr[2 * nj + 1][1] = t4[3];
            }
            #pragma unroll
            for (int mi = 0; mi < 2; mi++)
                #pragma unroll
                for (int ni = 0; ni < 8; ni++)
                    mma_s8(acc[mi][ni], af[mi], bfr[ni]);
        }
    }

    // Epilogue: plain stores of this K-split's s32 partial tile
    int gid = lane >> 2, tig = lane & 3;
    int* gdst = g_GvvP + ((size_t)bt * KSPLIT + kc) * TILE * TILE;
    #pragma unroll
    for (int mi = 0; mi < 2; mi++) {
        #pragma unroll
        for (int ni = 0; ni < 8; ni++) {
            int m = wm + mi * 16 + gid;
            int n = wn + ni * 8 + tig * 2;
            int* p = gdst + m * TILE + n;
            p[0] = acc[mi][ni][0];
            p[1] = acc[mi][ni][1];
            p[8 * TILE + 0] = acc[mi][ni][2];
            p[8 * TILE + 1] = acc[mi][ni][3];
        }
    }
}

// ---------------------------------------------------------------------------
// K3: parallel reduction + final output. 400 blocks.
// ---------------------------------------------------------------------------
__device__ float blockSum(float v) {
    __shared__ float sw[8];
    int lane = threadIdx.x & 31, w = threadIdx.x >> 5;
    __syncthreads();
    #pragma unroll
    for (int o = 16; o; o >>= 1) v += __shfl_xor_sync(0xffffffffu, v, o);
    if (lane == 0) sw[w] = v;
    __syncthreads();
    v = (threadIdx.x < 8) ? sw[threadIdx.x] : 0.0f;
    if (w == 0)
        #pragma unroll
        for (int o = 4; o; o >>= 1) v += __shfl_xor_sync(0xffu, v, o);
    return v;
}

__global__ __launch_bounds__(256) void k_red(float* __restrict__ out) {
    int bid = blockIdx.x, tid = threadIdx.x;
    const float invq2 = 1.0f / 16129.0f;   // 1/127^2
    if (bid < 384) {
        int bt = bid >> 3, seg = bid & 7;
        const int* g = g_GvvP + (size_t)bt * KSPLIT * TILE * TILE + seg * 2048;
        float total = 0.0f;
        #pragma unroll 2
        for (int i = tid; i < 2048; i += 256) {
            int xs = 0;
            #pragma unroll
            for (int kc = 0; kc < KSPLIT; kc++) xs += g[kc * TILE * TILE + i];
            float x = (float)xs * invq2;
            total += x * x;
        }
        total = blockSum(total);
        if (tid == 0) {
            float w = (bt % 3 == 1) ? 2.0f : 1.0f;  // off-diagonal tile counts twice
            atomicAdd(g_acc, w * total);
        }
    } else {
        int b = bid - 384;
        const float* gp = g_GvyP + (size_t)b * 32 * 1024;
        float gy = 0.0f;
        #pragma unroll
        for (int j = 0; j < 4; j++) {
            int o = tid + 256 * j;
            float x = 0.0f;
            #pragma unroll
            for (int ch = 0; ch < 32; ch++) x += gp[ch * 1024 + o];
            gy += x * x;
        }
        float c0 = 0, c1 = 0, c2 = 0, c3 = 0;
        for (int t = tid; t < T_; t += 256) {
            int s = g_cls[b * T_ + t];
            c0 += (s == 0); c1 += (s == 1); c2 += (s == 2); c3 += (s == 3);
        }
        gy = blockSum(gy);
        c0 = blockSum(c0); c1 = blockSum(c1); c2 = blockSum(c2); c3 = blockSum(c3);
        if (tid == 0)
            atomicAdd(g_acc, -2.0f * gy + c0 * c0 + c1 * c1 + c2 * c2 + c3 * c3);
    }
    if (tid == 0) {
        __threadfence();
        unsigned old = atomicAdd(&g_done, 1u);
        if (old == NRED - 1) {
            // divide by T*T*B = 2^32 (exact power of two)
            out[0] = g_acc[0] * 2.3283064365386963e-10f;
            g_acc[0] = 0.0f;
            g_done = 0u;
        }
    }
}

// ---------------------------------------------------------------------------
extern "C" void kernel_launch(void* const* d_in, const int* in_sizes, int n_in,
                              void* d_out, int out_size) {
    const float* emb = (const float*)d_in[0];
    const float* lab = (const float*)d_in[1];
    float* out = (float*)d_out;
    (void)in_sizes; (void)n_in; (void)out_size;

    const int smem_bytes = 4 * STAGE;   // 73728
    cudaFuncSetAttribute(k_gram, cudaFuncAttributeMaxDynamicSharedMemorySize, smem_bytes);

    k_norm<<<512, 256>>>(emb, lab);     // fused normalize + quantize + transpose + Gvy
    dim3 g2(48, KSPLIT);
    k_gram<<<g2, 256, smem_bytes>>>();
    k_red<<<NRED, 256>>>(out);
}

// round 12
// speedup vs baseline: 1.8701x; 1.7415x over previous
#include <cuda_runtime.h>
#include <cuda_bf16.h>
#include <cstdint>

// Problem constants
#define B_ 16
#define T_ 16384
#define D_ 256
#define S_ 4
#define TILE 128
#define KT 64
#define KSPLIT 6               // 48*6 = 288 CTAs = 2 per SM
#define PITCH 136              // 128 + 8 pad -> conflict-free ldmatrix.trans
#define MS (KT * PITCH)        // elements per smem matrix stage
#define NSTAGE 2

// Scratch (device globals; zero-initialized at load)
__device__ __nv_bfloat16 g_V[(size_t)B_ * T_ * D_];         // normalized V, bf16
__device__ unsigned char g_cls[B_ * T_];                     // speaker class per row
__device__ float g_GvvP[(size_t)48 * KSPLIT * TILE * TILE];  // K-split partials (18.9MB)
__device__ float g_GvyP[512 * 1024];                         // per-block Gvy partials (2MB)
__device__ float g_acc[1];
__device__ unsigned int g_done;
__device__ unsigned int g_cnt_b[16];    // per-batch norm-block counters
__device__ unsigned int g_cnt_bt[48];   // per-tile gram-CTA counters

// ---------------------------------------------------------------------------
__device__ float blockSum(float v) {
    __shared__ float sw[8];
    int lane = threadIdx.x & 31, w = threadIdx.x >> 5;
    __syncthreads();
    #pragma unroll
    for (int o = 16; o; o >>= 1) v += __shfl_xor_sync(0xffffffffu, v, o);
    if (lane == 0) sw[w] = v;
    __syncthreads();
    v = (threadIdx.x < 8) ? sw[threadIdx.x] : 0.0f;
    if (w == 0)
        #pragma unroll
        for (int o = 4; o; o >>= 1) v += __shfl_xor_sync(0xffu, v, o);
    return v;  // valid in thread 0
}

// ---------------------------------------------------------------------------
// K1: fused row-wise L2 normalize (fp32 -> bf16) + class extraction + Gvy
// partials. 512 blocks, 8 warps, warp = 64 rows processed 4 at a time.
// Last block per batch inline-reduces Gvy^2 + class counts into g_acc.
// ---------------------------------------------------------------------------
__global__ __launch_bounds__(256) void k_norm(const float* __restrict__ emb,
                                              const float* __restrict__ lab) {
    __shared__ float sred[8 * 1024];
    __shared__ int sflag;
    int b    = blockIdx.x >> 5;
    int ch   = blockIdx.x & 31;
    int wid  = threadIdx.x >> 5, lane = threadIdx.x & 31;
    int row0 = b * T_ + ch * 512 + wid * 64;

    // coalesced class pre-load: lane l handles rows row0+l and row0+32+l
    int s_lo, s_hi;
    {
        float4 lb = reinterpret_cast<const float4*>(lab)[row0 + lane];
        s_lo = lb.y > 0.5f ? 1 : (lb.z > 0.5f ? 2 : (lb.w > 0.5f ? 3 : 0));
        g_cls[row0 + lane] = (unsigned char)s_lo;
        float4 lb2 = reinterpret_cast<const float4*>(lab)[row0 + 32 + lane];
        s_hi = lb2.y > 0.5f ? 1 : (lb2.z > 0.5f ? 2 : (lb2.w > 0.5f ? 3 : 0));
        g_cls[row0 + 32 + lane] = (unsigned char)s_hi;
    }

    float acc[4][8];
    #pragma unroll
    for (int c = 0; c < 4; c++)
        #pragma unroll
        for (int i = 0; i < 8; i++) acc[c][i] = 0.0f;

    #pragma unroll 1
    for (int rb = 0; rb < 64; rb += 4) {
        // batch loads: 8 independent LDG.128 per lane
        float4 va[4][2];
        #pragma unroll
        for (int u = 0; u < 4; u++) {
            const float4* src = reinterpret_cast<const float4*>(emb)
                              + (size_t)(row0 + rb + u) * (D_ / 4) + lane * 2;
            va[u][0] = src[0];
            va[u][1] = src[1];
        }
        // 4 independent reductions, interleaved butterflies
        float ss[4];
        #pragma unroll
        for (int u = 0; u < 4; u++) {
            float4 v0 = va[u][0], v1 = va[u][1];
            ss[u] = v0.x*v0.x + v0.y*v0.y + v0.z*v0.z + v0.w*v0.w
                  + v1.x*v1.x + v1.y*v1.y + v1.z*v1.z + v1.w*v1.w;
        }
        #pragma unroll
        for (int o = 16; o; o >>= 1) {
            #pragma unroll
            for (int u = 0; u < 4; u++)
                ss[u] += __shfl_xor_sync(0xffffffffu, ss[u], o);
        }
        #pragma unroll
        for (int u = 0; u < 4; u++) {
            int r = rb + u;
            float sc = 1.0f / fmaxf(sqrtf(ss[u]), 1e-12f);
            float4 v0 = va[u][0], v1 = va[u][1];
            float n0 = v0.x * sc, n1 = v0.y * sc, n2 = v0.z * sc, n3 = v0.w * sc;
            float n4 = v1.x * sc, n5 = v1.y * sc, n6 = v1.z * sc, n7 = v1.w * sc;

            __nv_bfloat162 p0 = __floats2bfloat162_rn(n0, n1);
            __nv_bfloat162 p1 = __floats2bfloat162_rn(n2, n3);
            __nv_bfloat162 p2 = __floats2bfloat162_rn(n4, n5);
            __nv_bfloat162 p3 = __floats2bfloat162_rn(n6, n7);
            uint4 pk;
            pk.x = *reinterpret_cast<uint32_t*>(&p0);
            pk.y = *reinterpret_cast<uint32_t*>(&p1);
            pk.z = *reinterpret_cast<uint32_t*>(&p2);
            pk.w = *reinterpret_cast<uint32_t*>(&p3);
            reinterpret_cast<uint4*>(g_V)[(size_t)(row0 + r) * (D_ / 8) + lane] = pk;

            int s = __shfl_sync(0xffffffffu, r < 32 ? s_lo : s_hi, r & 31);
            #define ACCUM(C) { acc[C][0]+=n0; acc[C][1]+=n1; acc[C][2]+=n2; acc[C][3]+=n3; \
                               acc[C][4]+=n4; acc[C][5]+=n5; acc[C][6]+=n6; acc[C][7]+=n7; }
            if      (s == 0) ACCUM(0)
            else if (s == 1) ACCUM(1)
            else if (s == 2) ACCUM(2)
            else             ACCUM(3)
            #undef ACCUM
        }
    }

    // cross-warp reduce: sred[wid][(c*8+i)*32 + lane]  (conflict-free)
    #pragma unroll
    for (int c = 0; c < 4; c++)
        #pragma unroll
        for (int i = 0; i < 8; i++)
            sred[wid * 1024 + (c * 8 + i) * 32 + lane] = acc[c][i];
    __syncthreads();

    // per-block Gvy partial: plain coalesced stores
    float* gp = g_GvyP + (size_t)blockIdx.x * 1024;
    #pragma unroll
    for (int j = 0; j < 4; j++) {
        int o = threadIdx.x + 256 * j;
        float sum = 0.0f;
        #pragma unroll
        for (int w = 0; w < 8; w++) sum += sred[w * 1024 + o];
        gp[o] = sum;
    }

    // last block of this batch inline-reduces Gvy^2 + class counts
    __syncthreads();
    if (threadIdx.x == 0) {
        __threadfence();
        unsigned old = atomicAdd(&g_cnt_b[b], 1u);
        sflag = (old == 31u);
    }
    __syncthreads();
    if (sflag) {
        const float* gpb = g_GvyP + (size_t)b * 32 * 1024;
        float gy = 0.0f;
        #pragma unroll
        for (int j = 0; j < 4; j++) {
            int o = threadIdx.x + 256 * j;
            float x = 0.0f;
            #pragma unroll
            for (int chk = 0; chk < 32; chk++) x += gpb[chk * 1024 + o];
            gy += x * x;
        }
        float c0 = 0, c1 = 0, c2 = 0, c3 = 0;
        for (int t = threadIdx.x; t < T_; t += 256) {
            int s = g_cls[b * T_ + t];
            c0 += (s == 0); c1 += (s == 1); c2 += (s == 2); c3 += (s == 3);
        }
        gy = blockSum(gy);
        c0 = blockSum(c0); c1 = blockSum(c1); c2 = blockSum(c2); c3 = blockSum(c3);
        if (threadIdx.x == 0) {
            atomicAdd(g_acc, -2.0f * gy + c0 * c0 + c1 * c1 + c2 * c2 + c3 * c3);
            g_cnt_b[b] = 0;                       // reset for next graph replay
            __threadfence();
            atomicAdd(&g_done, 1u);               // units 1..16 (never final)
        }
    }
}

// ---------------------------------------------------------------------------
// PTX helpers
// ---------------------------------------------------------------------------
__device__ __forceinline__ void cp16(__nv_bfloat16* dst, const __nv_bfloat16* src) {
    unsigned d = (unsigned)__cvta_generic_to_shared(dst);
    asm volatile("cp.async.cg.shared.global [%0], [%1], 16;\n" :: "r"(d), "l"(src));
}
__device__ __forceinline__ void cp_commit() { asm volatile("cp.async.commit_group;\n"); }
template <int N> __device__ __forceinline__ void cp_wait() {
    asm volatile("cp.async.wait_group %0;\n" :: "n"(N));
}
__device__ __forceinline__ void ldsm4t(uint32_t* r, const __nv_bfloat16* p) {
    unsigned a = (unsigned)__cvta_generic_to_shared(p);
    asm volatile("ldmatrix.sync.aligned.m8n8.x4.trans.shared.b16 {%0,%1,%2,%3}, [%4];\n"
                 : "=r"(r[0]), "=r"(r[1]), "=r"(r[2]), "=r"(r[3]) : "r"(a));
}
__device__ __forceinline__ void mma_bf16(float* c, const uint32_t* a, const uint32_t* b) {
    asm volatile("mma.sync.aligned.m16n8k16.row.col.f32.bf16.bf16.f32 "
                 "{%0,%1,%2,%3},{%4,%5,%6,%7},{%8,%9},{%0,%1,%2,%3};\n"
                 : "+f"(c[0]), "+f"(c[1]), "+f"(c[2]), "+f"(c[3])
                 : "r"(a[0]), "r"(a[1]), "r"(a[2]), "r"(a[3]), "r"(b[0]), "r"(b[1]));
}

// ---------------------------------------------------------------------------
// K2: Gram tiles Gvv = V^T V. grid (48, 6) = 288 CTAs = 2/SM. R7 mainloop:
// 2-stage ring, one __syncthreads per iter. K-iters: 43,43,43,43,42,42.
// Last CTA per bt inline-reduces the 6 partials; global last unit writes out.
// ---------------------------------------------------------------------------
__global__ __launch_bounds__(256, 2) void k_gram(float* __restrict__ out) {
    extern __shared__ __nv_bfloat16 sm[];
    __shared__ int sflag;
    int bt   = blockIdx.x;
    int b    = bt / 3, tile = bt % 3;
    int ti   = (tile == 0) ? 0 : 1;
    int tj   = (tile == 2) ? 1 : 0;
    bool diag = (ti == tj);
    int kc   = blockIdx.y;
    int it0  = (kc < 4) ? 43 * kc : 172 + 42 * (kc - 4);
    int NIT  = (kc < 4) ? 43 : 42;
    int tid  = threadIdx.x;
    const __nv_bfloat16* gv = g_V + (size_t)b * T_ * D_;

    int wid = tid >> 5, lane = tid & 31;
    int wm = (wid & 3) * 32;
    int wn = (wid >> 2) * 64;
    int q = lane >> 3, rr = lane & 7;

    float acc[2][8][4];
    #pragma unroll
    for (int mi = 0; mi < 2; mi++)
        #pragma unroll
        for (int ni = 0; ni < 8; ni++)
            #pragma unroll
            for (int x = 0; x < 4; x++) acc[mi][ni][x] = 0.0f;

    auto load_stage = [&](int st, int iter) {
        size_t kofs = (size_t)(it0 + iter) * KT;
        const __nv_bfloat16* ga = gv + kofs * D_ + ti * TILE;
        __nv_bfloat16* sa = sm + st * MS;
        #pragma unroll
        for (int i = 0; i < 4; i++) {
            int c = tid + i * 256;
            int r = c >> 4, cc = c & 15;
            cp16(sa + r * PITCH + cc * 8, ga + r * D_ + cc * 8);
        }
        if (!diag) {
            const __nv_bfloat16* gb = gv + kofs * D_ + tj * TILE;
            __nv_bfloat16* sb = sm + (NSTAGE + st) * MS;
            #pragma unroll
            for (int i = 0; i < 4; i++) {
                int c = tid + i * 256;
                int r = c >> 4, cc = c & 15;
                cp16(sb + r * PITCH + cc * 8, gb + r * D_ + cc * 8);
            }
        }
        cp_commit();
    };

    load_stage(0, 0);

    for (int it = 0; it < NIT; ++it) {
        cp_wait<0>();          // stage (it&1) landed
        __syncthreads();       // all warps past compute(it-1): stage (it+1)&1 free
        if (it + 1 < NIT) load_stage((it + 1) & 1, it + 1);

        int st = it & 1;
        const __nv_bfloat16* As = sm + st * MS;
        const __nv_bfloat16* Bs = diag ? As : sm + (NSTAGE + st) * MS;
        #pragma unroll
        for (int ks = 0; ks < KT / 16; ++ks) {
            uint32_t af[2][4];
            #pragma unroll
            for (int mi = 0; mi < 2; mi++) {
                int dm   = wm + mi * 16;
                int krow = ks * 16 + ((q & 2) ? 8 : 0) + rr;
                int col  = dm + ((q & 1) ? 8 : 0);
                ldsm4t(af[mi], As + krow * PITCH + col);
            }
            uint32_t bfr[8][2];
            #pragma unroll
            for (int j = 0; j < 4; j++) {
                int n0   = wn + j * 16;
                int krow = ks * 16 + ((q & 1) ? 8 : 0) + rr;
                int col  = n0 + ((q & 2) ? 8 : 0);
                uint32_t t4[4];
                ldsm4t(t4, Bs + krow * PITCH + col);
                bfr[2 * j][0]     = t4[0]; bfr[2 * j][1]     = t4[1];
                bfr[2 * j + 1][0] = t4[2]; bfr[2 * j + 1][1] = t4[3];
            }
            #pragma unroll
            for (int mi = 0; mi < 2; mi++)
                #pragma unroll
                for (int ni = 0; ni < 8; ni++)
                    mma_bf16(acc[mi][ni], af[mi], bfr[ni]);
        }
    }

    // Epilogue: plain stores of this K-split's partial tile
    int gid = lane >> 2, tig = lane & 3;
    float* gdst = g_GvvP + ((size_t)bt * KSPLIT + kc) * TILE * TILE;
    #pragma unroll
    for (int mi = 0; mi < 2; mi++) {
        #pragma unroll
        for (int ni = 0; ni < 8; ni++) {
            int m = wm + mi * 16 + gid;
            int n = wn + ni * 8 + tig * 2;
            float* p = gdst + m * TILE + n;
            p[0] = acc[mi][ni][0];
            p[1] = acc[mi][ni][1];
            p[8 * TILE + 0] = acc[mi][ni][2];
            p[8 * TILE + 1] = acc[mi][ni][3];
        }
    }

    // last CTA of this bt inline-reduces the 6 partials (L2-hot)
    __syncthreads();
    if (tid == 0) {
        __threadfence();
        unsigned old = atomicAdd(&g_cnt_bt[bt], 1u);
        sflag = (old == KSPLIT - 1);
    }
    __syncthreads();
    if (sflag) {
        const float* g = g_GvvP + (size_t)bt * KSPLIT * TILE * TILE;
        float total = 0.0f;
        #pragma unroll 2
        for (int i = tid; i < TILE * TILE; i += 256) {
            float x = 0.0f;
            #pragma unroll
            for (int k2 = 0; k2 < KSPLIT; k2++) x += g[k2 * TILE * TILE + i];
            total += x * x;
        }
        total = blockSum(total);
        if (tid == 0) {
            float w = (tile == 1) ? 2.0f : 1.0f;  // off-diagonal tile counts twice
            atomicAdd(g_acc, w * total);
            g_cnt_bt[bt] = 0;                     // reset for next graph replay
            __threadfence();
            unsigned o2 = atomicAdd(&g_done, 1u);
            if (o2 == 63u) {                      // 16 norm + 48 gram units
                float fin = atomicAdd(g_acc, 0.0f);
                // divide by T*T*B = 2^32 (exact power of two)
                out[0] = fin * 2.3283064365386963e-10f;
                g_acc[0] = 0.0f;
                g_done = 0u;
            }
        }
    }
}

// ---------------------------------------------------------------------------
extern "C" void kernel_launch(void* const* d_in, const int* in_sizes, int n_in,
                              void* d_out, int out_size) {
    const float* emb = (const float*)d_in[0];
    const float* lab = (const float*)d_in[1];
    float* out = (float*)d_out;
    (void)in_sizes; (void)n_in; (void)out_size;

    const int smem_bytes = 2 * NSTAGE * MS * (int)sizeof(__nv_bfloat16);  // 69632
    cudaFuncSetAttribute(k_gram, cudaFuncAttributeMaxDynamicSharedMemorySize, smem_bytes);

    k_norm<<<512, 256>>>(emb, lab);   // fused normalize + Gvy partials + batch reduce
    dim3 g2(48, KSPLIT);
    k_gram<<<g2, 256, smem_bytes>>>(out);  // gram + tile reduce + final output
}

// round 13
// speedup vs baseline: 1.9640x; 1.0502x over previous
#include <cuda_runtime.h>
#include <cuda_bf16.h>
#include <cstdint>

// Problem constants
#define B_ 16
#define T_ 16384
#define D_ 256
#define S_ 4
#define TILE 128
#define KT 64
#define KSPLIT 6               // 48*6 = 288 CTAs = 2 per SM
#define PITCH 136              // 128 + 8 pad -> conflict-free ldmatrix.trans
#define MS (KT * PITCH)        // elements per smem matrix stage
#define NSTAGE 2
#define NRED 400               // 384 Gvv blocks + 16 Gvy/count blocks

// Scratch (device globals; zero-initialized at load)
__device__ __nv_bfloat16 g_V[(size_t)B_ * T_ * D_];         // normalized V, bf16
__device__ unsigned char g_cls[B_ * T_];                     // speaker class per row
__device__ float g_GvvP[(size_t)48 * KSPLIT * TILE * TILE];  // K-split partials (18.9MB)
__device__ float g_GvyP[512 * 1024];                         // per-block Gvy partials (2MB)
__device__ float g_acc[1];
__device__ unsigned int g_done;

// ---------------------------------------------------------------------------
// K1: fused row-wise L2 normalize (fp32 -> bf16) + class extraction + Gvy
// partials. 512 blocks, 8 warps, warp = 64 rows processed 4 at a time
// (batched LDG.128 + interleaved shfl butterflies).  [R9 tuned version]
// ---------------------------------------------------------------------------
__global__ __launch_bounds__(256) void k_norm(const float* __restrict__ emb,
                                              const float* __restrict__ lab) {
    __shared__ float sred[8 * 1024];
    int b    = blockIdx.x >> 5;
    int ch   = blockIdx.x & 31;
    int wid  = threadIdx.x >> 5, lane = threadIdx.x & 31;
    int row0 = b * T_ + ch * 512 + wid * 64;

    // coalesced class pre-load: lane l handles rows row0+l and row0+32+l
    int s_lo, s_hi;
    {
        float4 lb = reinterpret_cast<const float4*>(lab)[row0 + lane];
        s_lo = lb.y > 0.5f ? 1 : (lb.z > 0.5f ? 2 : (lb.w > 0.5f ? 3 : 0));
        g_cls[row0 + lane] = (unsigned char)s_lo;
        float4 lb2 = reinterpret_cast<const float4*>(lab)[row0 + 32 + lane];
        s_hi = lb2.y > 0.5f ? 1 : (lb2.z > 0.5f ? 2 : (lb2.w > 0.5f ? 3 : 0));
        g_cls[row0 + 32 + lane] = (unsigned char)s_hi;
    }

    float acc[4][8];
    #pragma unroll
    for (int c = 0; c < 4; c++)
        #pragma unroll
        for (int i = 0; i < 8; i++) acc[c][i] = 0.0f;

    #pragma unroll 1
    for (int rb = 0; rb < 64; rb += 4) {
        float4 va[4][2];
        #pragma unroll
        for (int u = 0; u < 4; u++) {
            const float4* src = reinterpret_cast<const float4*>(emb)
                              + (size_t)(row0 + rb + u) * (D_ / 4) + lane * 2;
            va[u][0] = src[0];
            va[u][1] = src[1];
        }
        float ss[4];
        #pragma unroll
        for (int u = 0; u < 4; u++) {
            float4 v0 = va[u][0], v1 = va[u][1];
            ss[u] = v0.x*v0.x + v0.y*v0.y + v0.z*v0.z + v0.w*v0.w
                  + v1.x*v1.x + v1.y*v1.y + v1.z*v1.z + v1.w*v1.w;
        }
        #pragma unroll
        for (int o = 16; o; o >>= 1) {
            #pragma unroll
            for (int u = 0; u < 4; u++)
                ss[u] += __shfl_xor_sync(0xffffffffu, ss[u], o);
        }
        #pragma unroll
        for (int u = 0; u < 4; u++) {
            int r = rb + u;
            float sc = 1.0f / fmaxf(sqrtf(ss[u]), 1e-12f);
            float4 v0 = va[u][0], v1 = va[u][1];
            float n0 = v0.x * sc, n1 = v0.y * sc, n2 = v0.z * sc, n3 = v0.w * sc;
            float n4 = v1.x * sc, n5 = v1.y * sc, n6 = v1.z * sc, n7 = v1.w * sc;

            __nv_bfloat162 p0 = __floats2bfloat162_rn(n0, n1);
            __nv_bfloat162 p1 = __floats2bfloat162_rn(n2, n3);
            __nv_bfloat162 p2 = __floats2bfloat162_rn(n4, n5);
            __nv_bfloat162 p3 = __floats2bfloat162_rn(n6, n7);
            uint4 pk;
            pk.x = *reinterpret_cast<uint32_t*>(&p0);
            pk.y = *reinterpret_cast<uint32_t*>(&p1);
            pk.z = *reinterpret_cast<uint32_t*>(&p2);
            pk.w = *reinterpret_cast<uint32_t*>(&p3);
            reinterpret_cast<uint4*>(g_V)[(size_t)(row0 + r) * (D_ / 8) + lane] = pk;

            int s = __shfl_sync(0xffffffffu, r < 32 ? s_lo : s_hi, r & 31);
            #define ACCUM(C) { acc[C][0]+=n0; acc[C][1]+=n1; acc[C][2]+=n2; acc[C][3]+=n3; \
                               acc[C][4]+=n4; acc[C][5]+=n5; acc[C][6]+=n6; acc[C][7]+=n7; }
            if      (s == 0) ACCUM(0)
            else if (s == 1) ACCUM(1)
            else if (s == 2) ACCUM(2)
            else             ACCUM(3)
            #undef ACCUM
        }
    }

    // cross-warp reduce: sred[wid][(c*8+i)*32 + lane]  (conflict-free)
    #pragma unroll
    for (int c = 0; c < 4; c++)
        #pragma unroll
        for (int i = 0; i < 8; i++)
            sred[wid * 1024 + (c * 8 + i) * 32 + lane] = acc[c][i];
    __syncthreads();

    float* gp = g_GvyP + (size_t)blockIdx.x * 1024;
    #pragma unroll
    for (int j = 0; j < 4; j++) {
        int o = threadIdx.x + 256 * j;
        float sum = 0.0f;
        #pragma unroll
        for (int w = 0; w < 8; w++) sum += sred[w * 1024 + o];
        gp[o] = sum;
    }
}

// ---------------------------------------------------------------------------
// PTX helpers
// ---------------------------------------------------------------------------
__device__ __forceinline__ void cp16(__nv_bfloat16* dst, const __nv_bfloat16* src) {
    unsigned d = (unsigned)__cvta_generic_to_shared(dst);
    asm volatile("cp.async.cg.shared.global [%0], [%1], 16;\n" :: "r"(d), "l"(src));
}
__device__ __forceinline__ void cp_commit() { asm volatile("cp.async.commit_group;\n"); }
template <int N> __device__ __forceinline__ void cp_wait() {
    asm volatile("cp.async.wait_group %0;\n" :: "n"(N));
}
__device__ __forceinline__ void ldsm4t(uint32_t* r, const __nv_bfloat16* p) {
    unsigned a = (unsigned)__cvta_generic_to_shared(p);
    asm volatile("ldmatrix.sync.aligned.m8n8.x4.trans.shared.b16 {%0,%1,%2,%3}, [%4];\n"
                 : "=r"(r[0]), "=r"(r[1]), "=r"(r[2]), "=r"(r[3]) : "r"(a));
}
__device__ __forceinline__ void mma_bf16(float* c, const uint32_t* a, const uint32_t* b) {
    asm volatile("mma.sync.aligned.m16n8k16.row.col.f32.bf16.bf16.f32 "
                 "{%0,%1,%2,%3},{%4,%5,%6,%7},{%8,%9},{%0,%1,%2,%3};\n"
                 : "+f"(c[0]), "+f"(c[1]), "+f"(c[2]), "+f"(c[3])
                 : "r"(a[0]), "r"(a[1]), "r"(a[2]), "r"(a[3]), "r"(b[0]), "r"(b[1]));
}

// ---------------------------------------------------------------------------
// K2: Gram tiles Gvv = V^T V. grid (48, 6) = 288 CTAs = 2/SM.
// 4 warps/CTA (128 threads), warp tile 64x64: halves smem crossbar traffic
// (the measured binder: tensor 45%, L1 41%) vs 8x(32x64).
// 2-stage ring, one __syncthreads/iter. K-iters: 43,43,43,43,42,42.
// ---------------------------------------------------------------------------
__global__ __launch_bounds__(128, 2) void k_gram() {
    extern __shared__ __nv_bfloat16 sm[];
    int bt   = blockIdx.x;
    int b    = bt / 3, tile = bt % 3;
    int ti   = (tile == 0) ? 0 : 1;
    int tj   = (tile == 2) ? 1 : 0;
    bool diag = (ti == tj);
    int kc   = blockIdx.y;
    int it0  = (kc < 4) ? 43 * kc : 172 + 42 * (kc - 4);
    int NIT  = (kc < 4) ? 43 : 42;
    int tid  = threadIdx.x;
    const __nv_bfloat16* gv = g_V + (size_t)b * T_ * D_;

    int wid = tid >> 5, lane = tid & 31;
    int wm = (wid & 1) * 64;
    int wn = (wid >> 1) * 64;
    int q = lane >> 3, rr = lane & 7;

    float acc[4][8][4];
    #pragma unroll
    for (int mi = 0; mi < 4; mi++)
        #pragma unroll
        for (int ni = 0; ni < 8; ni++)
            #pragma unroll
            for (int x = 0; x < 4; x++) acc[mi][ni][x] = 0.0f;

    auto load_stage = [&](int st, int iter) {
        size_t kofs = (size_t)(it0 + iter) * KT;
        const __nv_bfloat16* ga = gv + kofs * D_ + ti * TILE;
        __nv_bfloat16* sa = sm + st * MS;
        #pragma unroll
        for (int i = 0; i < 8; i++) {
            int c = tid + i * 128;
            int r = c >> 4, cc = c & 15;
            cp16(sa + r * PITCH + cc * 8, ga + r * D_ + cc * 8);
        }
        if (!diag) {
            const __nv_bfloat16* gb = gv + kofs * D_ + tj * TILE;
            __nv_bfloat16* sb = sm + (NSTAGE + st) * MS;
            #pragma unroll
            for (int i = 0; i < 8; i++) {
                int c = tid + i * 128;
                int r = c >> 4, cc = c & 15;
                cp16(sb + r * PITCH + cc * 8, gb + r * D_ + cc * 8);
            }
        }
        cp_commit();
    };

    load_stage(0, 0);

    for (int it = 0; it < NIT; ++it) {
        cp_wait<0>();          // stage (it&1) landed
        __syncthreads();       // all warps past compute(it-1): stage (it+1)&1 free
        if (it + 1 < NIT) load_stage((it + 1) & 1, it + 1);

        int st = it & 1;
        const __nv_bfloat16* As = sm + st * MS;
        const __nv_bfloat16* Bs = diag ? As : sm + (NSTAGE + st) * MS;
        #pragma unroll
        for (int ks = 0; ks < KT / 16; ++ks) {
            uint32_t af[4][4];
            #pragma unroll
            for (int mi = 0; mi < 4; mi++) {
                int dm   = wm + mi * 16;
                int krow = ks * 16 + ((q & 2) ? 8 : 0) + rr;
                int col  = dm + ((q & 1) ? 8 : 0);
                ldsm4t(af[mi], As + krow * PITCH + col);
            }
            uint32_t bfr[8][2];
            #pragma unroll
            for (int j = 0; j < 4; j++) {
                int n0   = wn + j * 16;
                int krow = ks * 16 + ((q & 1) ? 8 : 0) + rr;
                int col  = n0 + ((q & 2) ? 8 : 0);
                uint32_t t4[4];
                ldsm4t(t4, Bs + krow * PITCH + col);
                bfr[2 * j][0]     = t4[0]; bfr[2 * j][1]     = t4[1];
                bfr[2 * j + 1][0] = t4[2]; bfr[2 * j + 1][1] = t4[3];
            }
            #pragma unroll
            for (int mi = 0; mi < 4; mi++)
                #pragma unroll
                for (int ni = 0; ni < 8; ni++)
                    mma_bf16(acc[mi][ni], af[mi], bfr[ni]);
        }
    }

    // Epilogue: plain stores of this K-split's partial tile
    int gid = lane >> 2, tig = lane & 3;
    float* gdst = g_GvvP + ((size_t)bt * KSPLIT + kc) * TILE * TILE;
    #pragma unroll
    for (int mi = 0; mi < 4; mi++) {
        #pragma unroll
        for (int ni = 0; ni < 8; ni++) {
            int m = wm + mi * 16 + gid;
            int n = wn + ni * 8 + tig * 2;
            float* p = gdst + m * TILE + n;
            p[0] = acc[mi][ni][0];
            p[1] = acc[mi][ni][1];
            p[8 * TILE + 0] = acc[mi][ni][2];
            p[8 * TILE + 1] = acc[mi][ni][3];
        }
    }
}

// ---------------------------------------------------------------------------
// K3: parallel reduction + final output. 400 blocks. [R9 version]
// ---------------------------------------------------------------------------
__device__ float blockSum(float v) {
    __shared__ float sw[8];
    int lane = threadIdx.x & 31, w = threadIdx.x >> 5;
    __syncthreads();
    #pragma unroll
    for (int o = 16; o; o >>= 1) v += __shfl_xor_sync(0xffffffffu, v, o);
    if (lane == 0) sw[w] = v;
    __syncthreads();
    v = (threadIdx.x < 8) ? sw[threadIdx.x] : 0.0f;
    if (w == 0)
        #pragma unroll
        for (int o = 4; o; o >>= 1) v += __shfl_xor_sync(0xffu, v, o);
    return v;
}

__global__ __launch_bounds__(256) void k_red(float* __restrict__ out) {
    int bid = blockIdx.x, tid = threadIdx.x;
    if (bid < 384) {
        int bt = bid >> 3, seg = bid & 7;
        const float* g = g_GvvP + (size_t)bt * KSPLIT * TILE * TILE + seg * 2048;
        float total = 0.0f;
        #pragma unroll 2
        for (int i = tid; i < 2048; i += 256) {
            float x = 0.0f;
            #pragma unroll
            for (int kc = 0; kc < KSPLIT; kc++) x += g[kc * TILE * TILE + i];
            total += x * x;
        }
        total = blockSum(total);
        if (tid == 0) {
            float w = (bt % 3 == 1) ? 2.0f : 1.0f;  // off-diagonal tile counts twice
            atomicAdd(g_acc, w * total);
        }
    } else {
        int b = bid - 384;
        const float* gp = g_GvyP + (size_t)b * 32 * 1024;
        float gy = 0.0f;
        #pragma unroll
        for (int j = 0; j < 4; j++) {
            int o = tid + 256 * j;
            float x = 0.0f;
            #pragma unroll
            for (int ch = 0; ch < 32; ch++) x += gp[ch * 1024 + o];
            gy += x * x;
        }
        float c0 = 0, c1 = 0, c2 = 0, c3 = 0;
        for (int t = tid; t < T_; t += 256) {
            int s = g_cls[b * T_ + t];
            c0 += (s == 0); c1 += (s == 1); c2 += (s == 2); c3 += (s == 3);
        }
        gy = blockSum(gy);
        c0 = blockSum(c0); c1 = blockSum(c1); c2 = blockSum(c2); c3 = blockSum(c3);
        if (tid == 0)
            atomicAdd(g_acc, -2.0f * gy + c0 * c0 + c1 * c1 + c2 * c2 + c3 * c3);
    }
    if (tid == 0) {
        __threadfence();
        unsigned old = atomicAdd(&g_done, 1u);
        if (old == NRED - 1) {
            // divide by T*T*B = 2^32 (exact power of two)
            out[0] = g_acc[0] * 2.3283064365386963e-10f;
            g_acc[0] = 0.0f;
            g_done = 0u;
        }
    }
}

// ---------------------------------------------------------------------------
extern "C" void kernel_launch(void* const* d_in, const int* in_sizes, int n_in,
                              void* d_out, int out_size) {
    const float* emb = (const float*)d_in[0];
    const float* lab = (const float*)d_in[1];
    float* out = (float*)d_out;
    (void)in_sizes; (void)n_in; (void)out_size;

    const int smem_bytes = 2 * NSTAGE * MS * (int)sizeof(__nv_bfloat16);  // 69632
    cudaFuncSetAttribute(k_gram, cudaFuncAttributeMaxDynamicSharedMemorySize, smem_bytes);

    k_norm<<<512, 256>>>(emb, lab);        // fused normalize + Gvy partials
    dim3 g2(48, KSPLIT);
    k_gram<<<g2, 128, smem_bytes>>>();     // 4 warps, 64x64 warp tiles
    k_red<<<NRED, 256>>>(out);
}